// round 4
// baseline (speedup 1.0000x reference)
#include <cuda_runtime.h>

// out[t][l][d]: l==0 -> inputs[t][d], else memory[l][d]
// T=2048, L=64, D=1024 fp32. Pure store-bandwidth kernel (512 MiB writes).
//
// 256-bit ld/st (Blackwell LDG.E.256 / STG.E.256): each thread moves 32 B per
// op. 128 threads cover one 1 KiB row -> a 256-thread block does 2 rows per
// step, 8 rows total (grid 16384 = R2 winning shape). Streaming .cs stores
// keep the 258 KiB tail L2-resident; .nc loads.

static constexpr int T = 2048;
static constexpr int L = 64;
static constexpr int D8 = 1024 / 8;            // 128 float8 per row
static constexpr int ROWS = T * L;             // 131072
static constexpr int U = 8;                    // rows per block

struct f8 { float4 a, b; };

__device__ __forceinline__ f8 ldg256_nc(const float* p) {
    f8 v;
    asm volatile("ld.global.nc.v8.f32 {%0,%1,%2,%3,%4,%5,%6,%7}, [%8];"
                 : "=f"(v.a.x), "=f"(v.a.y), "=f"(v.a.z), "=f"(v.a.w),
                   "=f"(v.b.x), "=f"(v.b.y), "=f"(v.b.z), "=f"(v.b.w)
                 : "l"(p));
    return v;
}

__device__ __forceinline__ void stg256_cs(float* p, const f8& v) {
    asm volatile("st.global.cs.v8.f32 [%0], {%1,%2,%3,%4,%5,%6,%7,%8};"
                 :: "l"(p),
                    "f"(v.a.x), "f"(v.a.y), "f"(v.a.z), "f"(v.a.w),
                    "f"(v.b.x), "f"(v.b.y), "f"(v.b.z), "f"(v.b.w)
                 : "memory");
}

__global__ __launch_bounds__(256, 8)
void sliding_window_memory_kernel(const float* __restrict__ in,
                                  const float* __restrict__ mem,
                                  float* __restrict__ out)
{
    const int tid = threadIdx.x;           // 0..255
    const int d8  = tid & (D8 - 1);        // 0..127: float8 index in row
    const int rsub = tid >> 7;             // 0 or 1: row within pair
    const int row0 = blockIdx.x * U + rsub;

    float* __restrict__ o = out + (long)row0 * (D8 * 8) + d8 * 8;

    f8 v[U / 2];
#pragma unroll
    for (int u = 0; u < U / 2; ++u) {
        const int row = row0 + u * 2;      // this thread's rows: row0, row0+2, ...
        const int l = row & (L - 1);
        const int t = row >> 6;
        const float* s = (l == 0) ? (in + t * (D8 * 8) + d8 * 8)
                                  : (mem + l * (D8 * 8) + d8 * 8);
        v[u] = ldg256_nc(s);               // in: DRAM once; tail: L2-resident
    }
#pragma unroll
    for (int u = 0; u < U / 2; ++u) {
        stg256_cs(o + (long)u * 2 * (D8 * 8), v[u]);
    }
}

extern "C" void kernel_launch(void* const* d_in, const int* in_sizes, int n_in,
                              void* d_out, int out_size)
{
    const float* in  = (const float*)d_in[0];   // inputs [T, D] fp32
    const float* mem = (const float*)d_in[1];   // memory [L, D] fp32
    float* out = (float*)d_out;                 // [T, L, D] fp32

    const int threads = 256;
    const int blocks = ROWS / U;                // 16384
    sliding_window_memory_kernel<<<blocks, threads>>>(in, mem, out);
}

// round 5
// speedup vs baseline: 1.0554x; 1.0554x over previous
#include <cuda_runtime.h>

// out[t][l][d]: l==0 -> inputs[t][d], else memory[l][d].
// T=2048, L=64, D=1024 fp32. 512 MiB compulsory writes.
//
// Key insight: tail rows (l>0) are constant across t. Previous mapping re-read
// each tail row from L2 for every t (504 MiB of LTS read traffic on top of the
// 512 MiB of writes). New mapping: block = (l, t-chunk). A block with l>0
// loads its 4 KiB row ONCE into registers, then streams it to TC t-slots.
// L2 read traffic: 504 MiB -> ~8 MiB.

static constexpr int T  = 2048;
static constexpr int L  = 64;
static constexpr int D4 = 1024 / 4;      // 256 float4 per row (4 KiB)
static constexpr int TC = 16;            // t-slots per block
static constexpr long ROW_STRIDE = (long)L * D4;  // float4s per t

__global__ __launch_bounds__(256, 8)
void sliding_window_memory_kernel(const float4* __restrict__ in,
                                  const float4* __restrict__ mem,
                                  float4* __restrict__ out)
{
    const int tid = threadIdx.x;               // = d4 index, 0..255
    const int l   = blockIdx.x & (L - 1);      // 0..63
    const int t0  = (blockIdx.x >> 6) * TC;    // chunk start

    float4* __restrict__ o = out + (long)t0 * ROW_STRIDE + (long)l * D4 + tid;

    if (l != 0) {
        // constant across t: load once, store TC times
        const float4 v = __ldg(mem + l * D4 + tid);
#pragma unroll
        for (int u = 0; u < TC; ++u) {
            __stcs(o + (long)u * ROW_STRIDE, v);   // streaming: bypass L2 reuse
        }
    } else {
        // slot 0: per-t copy of inputs[t]
        const float4* __restrict__ s = in + (long)t0 * D4 + tid;
        float4 v[TC];
#pragma unroll
        for (int u = 0; u < TC; ++u) v[u] = __ldg(s + (long)u * D4);
#pragma unroll
        for (int u = 0; u < TC; ++u) __stcs(o + (long)u * ROW_STRIDE, v[u]);
    }
}

extern "C" void kernel_launch(void* const* d_in, const int* in_sizes, int n_in,
                              void* d_out, int out_size)
{
    const float4* in  = (const float4*)d_in[0];   // inputs [T, D] fp32
    const float4* mem = (const float4*)d_in[1];   // memory [L, D] fp32
    float4* out = (float4*)d_out;                 // [T, L, D] fp32

    const int threads = 256;
    const int blocks = (T / TC) * L;              // 128 * 64 = 8192
    sliding_window_memory_kernel<<<blocks, threads>>>(in, mem, out);
}